// round 2
// baseline (speedup 1.0000x reference)
#include <cuda_runtime.h>
#include <math.h>

// ---------------- problem constants ----------------
#define NND 32768
#define NE  262144
#define NS  128
#define NB  16
#define D_0 190
#define D_X 380
#define D_GIN 256
#define D_GH 512

// ---------------- device scratch (static, no allocation) ----------------
__device__ float g_x0[(size_t)NND * D_0];
__device__ float g_x1[(size_t)NND * D_X];
__device__ float g_x2[(size_t)NND * D_GIN];
__device__ float g_xa[(size_t)NND * D_GH];
__device__ float g_xb[(size_t)NND * D_GH];
__device__ float g_agg[(size_t)NND * D_GH];
__device__ float g_invdeg[NND];
__device__ int   g_segid[NND];
__device__ float g_glnstat[NS * 2];      // mean, inv-std per segment
__device__ float g_colsum[D_GH];
__device__ float g_pnmean[D_GH];
__device__ float g_scalar[2];            // [0]=sumsq total, [1]=1/denom
__device__ float g_segout[NS];

// ---------------- small utility kernels ----------------
__global__ void k_zero(float* p, size_t n) {
    size_t i = (size_t)blockIdx.x * blockDim.x + threadIdx.x;
    if (i < n) p[i] = 0.f;
}

// seg_id via binary search over node_separation; also zero deg accumulator
__global__ void k_segid(const int* __restrict__ sep) {
    int i = blockIdx.x * blockDim.x + threadIdx.x;
    if (i >= NND) return;
    int lo = 0, hi = NS;
    while (lo < hi) {
        int mid = (lo + hi) >> 1;
        if (sep[mid] <= i) lo = mid + 1; else hi = mid;
    }
    g_segid[i] = lo;
    g_invdeg[i] = 0.f;
}

__global__ void k_deg(const int* __restrict__ dst) {
    int e = blockIdx.x * blockDim.x + threadIdx.x;
    if (e < NE) atomicAdd(&g_invdeg[dst[e]], 1.f);
}

__global__ void k_invdeg() {
    int i = blockIdx.x * blockDim.x + threadIdx.x;
    if (i < NND) g_invdeg[i] = 1.f / fmaxf(g_invdeg[i], 1.f);
}

// concat [node_features | node_config_features | emb_table[node_ops]]
__global__ void k_concat(const float* __restrict__ nf, const float* __restrict__ ncf,
                         const float* __restrict__ emb, const int* __restrict__ ops) {
    size_t i = (size_t)blockIdx.x * blockDim.x + threadIdx.x;
    if (i >= (size_t)NND * D_0) return;
    int r = (int)(i / D_0);
    int c = (int)(i - (size_t)r * D_0);
    float v;
    if (c < 90)       v = nf[(size_t)r * 90 + c];
    else if (c < 126) v = ncf[(size_t)r * 36 + (c - 90)];
    else              v = emb[(size_t)ops[r] * 64 + (c - 126)];
    g_x0[i] = v;
}

// ---------------- tiled fp32 GEMM:  C[M,Nd] (+)= A[M,K] @ W[Nd,K]^T ----------------
// flags: 1 = accumulate into C, 2 = leaky-relu epilogue
__global__ void __launch_bounds__(256)
k_gemm(const float* __restrict__ A, const float* __restrict__ W,
       const float* __restrict__ bias, float* __restrict__ C,
       int M, int K, int Nd, int flags) {
    __shared__ float As[8][128];
    __shared__ float Ws[8][128];
    const int tid = threadIdx.x;
    const int bm = blockIdx.y * 128;
    const int bn = blockIdx.x * 128;
    const int tr = (tid >> 4) << 3;   // 0..120
    const int tc = (tid & 15) << 3;   // 0..120

    float acc[8][8];
#pragma unroll
    for (int i = 0; i < 8; i++)
#pragma unroll
        for (int j = 0; j < 8; j++) acc[i][j] = 0.f;

    const int lr  = (tid * 4) >> 3;   // row within tile for loads
    const int lk0 = (tid * 4) & 7;    // k offset (0 or 4)

    for (int k0 = 0; k0 < K; k0 += 8) {
#pragma unroll
        for (int i = 0; i < 4; i++) {
            int kk = lk0 + i;
            int gk = k0 + kk;
            int gr = bm + lr;
            int gn = bn + lr;
            As[kk][lr] = (gk < K && gr < M) ? A[(size_t)gr * K + gk] : 0.f;
            Ws[kk][lr] = (gk < K && gn < Nd) ? W[(size_t)gn * K + gk] : 0.f;
        }
        __syncthreads();
#pragma unroll
        for (int kk = 0; kk < 8; kk++) {
            float4 a0 = *(const float4*)&As[kk][tr];
            float4 a1 = *(const float4*)&As[kk][tr + 4];
            float4 b0 = *(const float4*)&Ws[kk][tc];
            float4 b1 = *(const float4*)&Ws[kk][tc + 4];
            float a[8] = {a0.x, a0.y, a0.z, a0.w, a1.x, a1.y, a1.z, a1.w};
            float b[8] = {b0.x, b0.y, b0.z, b0.w, b1.x, b1.y, b1.z, b1.w};
#pragma unroll
            for (int i = 0; i < 8; i++)
#pragma unroll
                for (int j = 0; j < 8; j++)
                    acc[i][j] = fmaf(a[i], b[j], acc[i][j]);
        }
        __syncthreads();
    }

#pragma unroll
    for (int i = 0; i < 8; i++) {
        int gr = bm + tr + i;
        if (gr >= M) continue;
        float* Crow = &C[(size_t)gr * Nd];
#pragma unroll
        for (int j = 0; j < 8; j++) {
            int gn = bn + tc + j;
            if (gn >= Nd) continue;
            float v = acc[i][j];
            if (bias) v += bias[gn];
            if (flags & 1) v += Crow[gn];
            if (flags & 2) v = (v >= 0.f) ? v : 0.01f * v;
            Crow[gn] = v;
        }
    }
}

// ---------------- graph-wise layernorm ----------------
__global__ void k_glnstats(const float* __restrict__ x, const int* __restrict__ sep, int D) {
    int s = blockIdx.x;
    int start = (s == 0) ? 0 : sep[s - 1];
    int end = sep[s];
    size_t total = (size_t)(end - start) * D;
    const float* base = &x[(size_t)start * D];
    float sum = 0.f, ss = 0.f;
    for (size_t i = threadIdx.x; i < total; i += blockDim.x) {
        float v = base[i];
        sum += v; ss += v * v;
    }
    __shared__ float s1[256], s2[256];
    int t = threadIdx.x;
    s1[t] = sum; s2[t] = ss;
    __syncthreads();
    for (int o = 128; o > 0; o >>= 1) {
        if (t < o) { s1[t] += s1[t + o]; s2[t] += s2[t + o]; }
        __syncthreads();
    }
    if (t == 0) {
        float cnt = (float)total;
        float mean = s1[0] / cnt;
        float var = s2[0] / cnt - mean * mean;
        g_glnstat[2 * s] = mean;
        g_glnstat[2 * s + 1] = rsqrtf(var + 1e-5f);
    }
}

__global__ void k_glnapply(float* __restrict__ x, const float* __restrict__ gamma,
                           const float* __restrict__ beta, int D) {
    int r = blockIdx.x;
    int f = blockIdx.y * blockDim.x + threadIdx.x;
    if (f >= D) return;
    int s = g_segid[r];
    size_t i = (size_t)r * D + f;
    x[i] = (x[i] - g_glnstat[2 * s]) * g_glnstat[2 * s + 1] * gamma[f] + beta[f];
}

// ---------------- edge aggregation ----------------
__global__ void k_scatter(const float* __restrict__ x, const int* __restrict__ src,
                          const int* __restrict__ dst, int D) {
    int e = blockIdx.x;
    int f4 = blockIdx.y * blockDim.x + threadIdx.x;   // float4 index
    if (f4 >= (D >> 2)) return;
    int s = src[e], d = dst[e];
    float4 v = *(const float4*)&x[(size_t)s * D + f4 * 4];
#if __CUDA_ARCH__ >= 900
    atomicAdd((float4*)&g_agg[(size_t)d * D + f4 * 4], v);
#else
    float* p = &g_agg[(size_t)d * D + f4 * 4];
    atomicAdd(p + 0, v.x); atomicAdd(p + 1, v.y);
    atomicAdd(p + 2, v.z); atomicAdd(p + 3, v.w);
#endif
}

__global__ void k_scale(int D) {
    int r = blockIdx.x;
    int f = blockIdx.y * blockDim.x + threadIdx.x;
    if (f < D) g_agg[(size_t)r * D + f] *= g_invdeg[r];
}

// ---------------- PairNorm ----------------
__global__ void k_pnstats(const float* __restrict__ x) {
    int r0 = blockIdx.x * 128;
    int t = threadIdx.x;
    float c1 = 0.f, c2 = 0.f, sq = 0.f;
    for (int r = 0; r < 128; r++) {
        const float* row = &x[(size_t)(r0 + r) * D_GH];
        float v1 = row[t], v2 = row[t + 256];
        c1 += v1; c2 += v2;
        sq += v1 * v1 + v2 * v2;
    }
    atomicAdd(&g_colsum[t], c1);
    atomicAdd(&g_colsum[t + 256], c2);
    __shared__ float sh[256];
    sh[t] = sq;
    __syncthreads();
    for (int o = 128; o > 0; o >>= 1) {
        if (t < o) sh[t] += sh[t + o];
        __syncthreads();
    }
    if (t == 0) atomicAdd(&g_scalar[0], sh[0]);
}

__global__ void k_pnfin() {
    int t = threadIdx.x;   // 512 threads
    float m = g_colsum[t] / (float)NND;
    g_pnmean[t] = m;
    __shared__ float sh[512];
    sh[t] = m * m;
    __syncthreads();
    for (int o = 256; o > 0; o >>= 1) {
        if (t < o) sh[t] += sh[t + o];
        __syncthreads();
    }
    if (t == 0) {
        float var = g_scalar[0] / (float)NND - sh[0];
        g_scalar[1] = 1.f / (1e-5f + sqrtf(fmaxf(var, 0.f)));
    }
}

__global__ void k_pnapply(const float* __restrict__ in, float* __restrict__ out) {
    size_t i = (size_t)blockIdx.x * blockDim.x + threadIdx.x;
    if (i >= (size_t)NND * D_GH) return;
    int f = (int)(i & (D_GH - 1));
    float v = (in[i] - g_pnmean[f]) * g_scalar[1];
    out[i] = fmaxf(v, 0.f);
}

// ---------------- final pooling + linear ----------------
__global__ void k_finaldot(const float* __restrict__ x, const float* __restrict__ wc) {
    int gt = blockIdx.x * blockDim.x + threadIdx.x;
    int node = gt >> 5;
    int lane = gt & 31;
    if (node >= NND) return;
    const float* row = &x[(size_t)node * D_GH];
    float s = 0.f;
#pragma unroll
    for (int k = 0; k < 16; k++) s += row[k * 32 + lane] * wc[k * 32 + lane];
#pragma unroll
    for (int o = 16; o > 0; o >>= 1) s += __shfl_xor_sync(0xFFFFFFFFu, s, o);
    if (lane == 0) atomicAdd(&g_segout[g_segid[node]], s);
}

__global__ void k_out(float* __restrict__ out, const float* __restrict__ bc) {
    int t = threadIdx.x;
    if (t < NS) out[t] = g_segout[t] + bc[0];
}

// ---------------- host orchestration ----------------
static inline void launch_gemm(const float* A, const float* W, const float* bias,
                               float* C, int M, int K, int Nd, int flags) {
    dim3 grid((Nd + 127) / 128, (M + 127) / 128);
    k_gemm<<<grid, 256>>>(A, W, bias, C, M, K, Nd, flags);
}

extern "C" void kernel_launch(void* const* d_in, const int* in_sizes, int n_in,
                              void* d_out, int out_size) {
    const float* nf   = (const float*)d_in[0];
    const float* ncf  = (const float*)d_in[1];
    const float* emb  = (const float*)d_in[2];
    const float* w1   = (const float*)d_in[3];
    const float* b1   = (const float*)d_in[4];
    const float* g1   = (const float*)d_in[5];
    const float* be1  = (const float*)d_in[6];
    const float* w2   = (const float*)d_in[7];
    const float* b2   = (const float*)d_in[8];
    const float* g2   = (const float*)d_in[9];
    const float* be2  = (const float*)d_in[10];
    const float* wl1  = (const float*)d_in[11];
    const float* bl1  = (const float*)d_in[12];
    const float* wr1  = (const float*)d_in[13];
    const float* wl2  = (const float*)d_in[14];
    const float* bl2  = (const float*)d_in[15];
    const float* wr2  = (const float*)d_in[16];
    const float* wl3  = (const float*)d_in[17];
    const float* bl3  = (const float*)d_in[18];
    const float* wr3  = (const float*)d_in[19];
    const float* wc   = (const float*)d_in[20];
    const float* bc   = (const float*)d_in[21];
    const int* ops    = (const int*)d_in[22];
    const int* edges  = (const int*)d_in[23];
    const int* sep    = (const int*)d_in[24];
    float* out        = (float*)d_out;

    const int* src = edges;
    const int* dst = edges + NE;

    // scratch addresses for zero kernels
    void *p_agg, *p_colsum, *p_scalar, *p_segout, *p_x0, *p_x1, *p_x2, *p_xa, *p_xb;
    cudaGetSymbolAddress(&p_agg, g_agg);
    cudaGetSymbolAddress(&p_colsum, g_colsum);
    cudaGetSymbolAddress(&p_scalar, g_scalar);
    cudaGetSymbolAddress(&p_segout, g_segout);
    cudaGetSymbolAddress(&p_x0, g_x0);
    cudaGetSymbolAddress(&p_x1, g_x1);
    cudaGetSymbolAddress(&p_x2, g_x2);
    cudaGetSymbolAddress(&p_xa, g_xa);
    cudaGetSymbolAddress(&p_xb, g_xb);
    float* d_agg = (float*)p_agg;
    float* d_x0 = (float*)p_x0;
    float* d_x1 = (float*)p_x1;
    float* d_x2 = (float*)p_x2;
    float* d_xa = (float*)p_xa;
    float* d_xb = (float*)p_xb;

    // ---- prep: seg ids, degrees, input concat ----
    k_segid<<<(NND + 255) / 256, 256>>>(sep);
    k_deg<<<(NE + 255) / 256, 256>>>(dst);
    k_invdeg<<<(NND + 255) / 256, 256>>>();
    {
        size_t n = (size_t)NND * D_0;
        k_concat<<<(unsigned)((n + 255) / 256), 256>>>(nf, ncf, emb, ops);
    }

    // ---- MLP layer 1: leaky(x0 @ w1^T + b1) then graphwise LN ----
    launch_gemm(d_x0, w1, b1, d_x1, NND, D_0, D_X, /*leaky*/2);
    k_glnstats<<<NS, 256>>>(d_x1, sep, D_X);
    k_glnapply<<<dim3(NND, (D_X + 255) / 256), 256>>>(d_x1, g1, be1, D_X);

    // ---- MLP layer 2 ----
    launch_gemm(d_x1, w2, b2, d_x2, NND, D_X, D_GIN, 2);
    k_glnstats<<<NS, 256>>>(d_x2, sep, D_GIN);
    k_glnapply<<<dim3(NND, (D_GIN + 255) / 256), 256>>>(d_x2, g2, be2, D_GIN);

    // ---- SAGE layer 1 (K = 256) ----
    {
        size_t n = (size_t)NND * D_GIN;
        k_zero<<<(unsigned)((n + 255) / 256), 256>>>(d_agg, n);
        k_scatter<<<dim3(NE, 1), 64>>>(d_x2, src, dst, D_GIN);      // 256/4 = 64 float4
        k_scale<<<dim3(NND, 1), 256>>>(D_GIN);
        launch_gemm(d_agg, wl1, bl1, d_xb, NND, D_GIN, D_GH, 0);
        launch_gemm(d_x2, wr1, nullptr, d_xb, NND, D_GIN, D_GH, /*acc*/1);
        k_zero<<<3, 256>>>((float*)p_colsum, D_GH);
        k_zero<<<1, 2>>>((float*)p_scalar, 2);
        k_pnstats<<<NND / 128, 256>>>(d_xb);
        k_pnfin<<<1, 512>>>();
        size_t m = (size_t)NND * D_GH;
        k_pnapply<<<(unsigned)((m + 255) / 256), 256>>>(d_xb, d_xa);
    }

    // ---- SAGE layer 2 (K = 512) ----
    {
        size_t n = (size_t)NND * D_GH;
        k_zero<<<(unsigned)((n + 255) / 256), 256>>>(d_agg, n);
        k_scatter<<<dim3(NE, 1), 128>>>(d_xa, src, dst, D_GH);      // 512/4 = 128 float4
        k_scale<<<dim3(NND, 2), 256>>>(D_GH);
        launch_gemm(d_agg, wl2, bl2, d_xb, NND, D_GH, D_GH, 0);
        launch_gemm(d_xa, wr2, nullptr, d_xb, NND, D_GH, D_GH, 1);
        k_zero<<<3, 256>>>((float*)p_colsum, D_GH);
        k_zero<<<1, 2>>>((float*)p_scalar, 2);
        k_pnstats<<<NND / 128, 256>>>(d_xb);
        k_pnfin<<<1, 512>>>();
        k_pnapply<<<(unsigned)((n + 255) / 256), 256>>>(d_xb, d_xa);
    }

    // ---- SAGE layer 3 (K = 512, no pairnorm/relu) ----
    {
        size_t n = (size_t)NND * D_GH;
        k_zero<<<(unsigned)((n + 255) / 256), 256>>>(d_agg, n);
        k_scatter<<<dim3(NE, 1), 128>>>(d_xa, src, dst, D_GH);
        k_scale<<<dim3(NND, 2), 256>>>(D_GH);
        launch_gemm(d_agg, wl3, bl3, d_xb, NND, D_GH, D_GH, 0);
        launch_gemm(d_xa, wr3, nullptr, d_xb, NND, D_GH, D_GH, 1);
    }

    // ---- segment pooling + final linear ----
    k_zero<<<1, NS>>>((float*)p_segout, NS);
    k_finaldot<<<(NND * 32) / 256, 256>>>(d_xb, wc);
    k_out<<<1, NS>>>(out, bc);
}

// round 4
// speedup vs baseline: 2.1819x; 2.1819x over previous
#include <cuda_runtime.h>
#include <cuda_bf16.h>
#include <math.h>
#include <stdint.h>

// ---------------- problem constants ----------------
#define NND 32768
#define NE  262144
#define NS  128
#define D_0 190
#define D_X 380
#define D_GIN 256
#define D_GH 512

// ---------------- device scratch (static, no allocation) ----------------
__device__ __align__(128) float g_x0[(size_t)NND * D_0];
__device__ __align__(128) float g_x1[(size_t)NND * D_X];
__device__ __align__(128) float g_x2[(size_t)NND * D_GIN];
__device__ __align__(128) float g_xa[(size_t)NND * D_GH];
__device__ __align__(128) float g_xb[(size_t)NND * D_GH];
__device__ __align__(128) float g_agg[(size_t)NND * D_GH];
__device__ __align__(128) __nv_bfloat16 g_ahi[(size_t)NND * 512];
__device__ __align__(128) __nv_bfloat16 g_alo[(size_t)NND * 512];
__device__ __align__(128) __nv_bfloat16 g_whi[512 * 512];
__device__ __align__(128) __nv_bfloat16 g_wlo[512 * 512];
__device__ float g_invdeg[NND];
__device__ int   g_segid[NND];
__device__ float g_glnstat[NS * 2];
__device__ float g_colsum[D_GH];
__device__ float g_pnmean[D_GH];
__device__ float g_scalar[2];
__device__ float g_segout[NS];

// ---------------- PTX helpers (compute_103-safe: no 'a' features) ----------------
__device__ __forceinline__ uint32_t smem_u32(const void* p) {
    uint32_t a;
    asm("{ .reg .u64 t; cvta.to.shared.u64 t, %1; cvt.u32.u64 %0, t; }" : "=r"(a) : "l"(p));
    return a;
}
__device__ __forceinline__ void cpasync16(uint32_t dst, const void* src) {
    asm volatile("cp.async.cg.shared.global [%0], [%1], 16;" :: "r"(dst), "l"(src) : "memory");
}
__device__ __forceinline__ void ldm_x4(uint32_t* r, uint32_t addr) {
    asm volatile("ldmatrix.sync.aligned.m8n8.x4.shared.b16 {%0,%1,%2,%3},[%4];"
                 : "=r"(r[0]), "=r"(r[1]), "=r"(r[2]), "=r"(r[3]) : "r"(addr));
}
__device__ __forceinline__ void ldm_x2(uint32_t* r, uint32_t addr) {
    asm volatile("ldmatrix.sync.aligned.m8n8.x2.shared.b16 {%0,%1},[%2];"
                 : "=r"(r[0]), "=r"(r[1]) : "r"(addr));
}
__device__ __forceinline__ void mma_bf16(float* d, const uint32_t* a, const uint32_t* b) {
    asm volatile(
        "mma.sync.aligned.m16n8k16.row.col.f32.bf16.bf16.f32 "
        "{%0,%1,%2,%3}, {%4,%5,%6,%7}, {%8,%9}, {%0,%1,%2,%3};"
        : "+f"(d[0]), "+f"(d[1]), "+f"(d[2]), "+f"(d[3])
        : "r"(a[0]), "r"(a[1]), "r"(a[2]), "r"(a[3]), "r"(b[0]), "r"(b[1]));
}

// ---------------- small utility kernels ----------------
__global__ void k_zero(float* p, size_t n) {
    size_t i = (size_t)blockIdx.x * blockDim.x + threadIdx.x;
    if (i < n) p[i] = 0.f;
}
__global__ void k_segid(const int* __restrict__ sep) {
    int i = blockIdx.x * blockDim.x + threadIdx.x;
    if (i >= NND) return;
    int lo = 0, hi = NS;
    while (lo < hi) { int mid = (lo + hi) >> 1; if (sep[mid] <= i) lo = mid + 1; else hi = mid; }
    g_segid[i] = lo;
    g_invdeg[i] = 0.f;
}
__global__ void k_deg(const int* __restrict__ dst) {
    int e = blockIdx.x * blockDim.x + threadIdx.x;
    if (e < NE) atomicAdd(&g_invdeg[dst[e]], 1.f);
}
__global__ void k_invdeg() {
    int i = blockIdx.x * blockDim.x + threadIdx.x;
    if (i < NND) g_invdeg[i] = 1.f / fmaxf(g_invdeg[i], 1.f);
}
__global__ void k_concat(const float* __restrict__ nf, const float* __restrict__ ncf,
                         const float* __restrict__ emb, const int* __restrict__ ops) {
    size_t i = (size_t)blockIdx.x * blockDim.x + threadIdx.x;
    if (i >= (size_t)NND * D_0) return;
    int r = (int)(i / D_0);
    int c = (int)(i - (size_t)r * D_0);
    float v;
    if (c < 90)       v = nf[(size_t)r * 90 + c];
    else if (c < 126) v = ncf[(size_t)r * 36 + (c - 90)];
    else              v = emb[(size_t)ops[r] * 64 + (c - 126)];
    g_x0[i] = v;
}

// ---------------- bf16 hi/lo split converts ----------------
__global__ void k_cvtA(const float* __restrict__ X, __nv_bfloat16* __restrict__ hi,
                       __nv_bfloat16* __restrict__ lo, int M, int K, int Kp) {
    int idx = blockIdx.x * blockDim.x + threadIdx.x;
    if (idx >= M * Kp) return;
    int m = idx / Kp, k = idx - m * Kp;
    float v = (k < K) ? X[(size_t)m * K + k] : 0.f;
    __nv_bfloat16 h = __float2bfloat16(v);
    hi[idx] = h;
    lo[idx] = __float2bfloat16(v - __bfloat162float(h));
}
__global__ void k_cvtW(const float* __restrict__ W, __nv_bfloat16* __restrict__ hi,
                       __nv_bfloat16* __restrict__ lo, int Nd, int K, int Ndp, int Kp) {
    int idx = blockIdx.x * blockDim.x + threadIdx.x;
    if (idx >= Ndp * Kp) return;
    int n = idx / Kp, k = idx - n * Kp;
    float v = (n < Nd && k < K) ? W[(size_t)n * K + k] : 0.f;
    __nv_bfloat16 h = __float2bfloat16(v);
    hi[idx] = h;
    lo[idx] = __float2bfloat16(v - __bfloat162float(h));
}

// ---------------- mma.sync bf16x3 GEMM:  C[M,Nd] (+)= A[M,K] @ W[Nd,K]^T --------
// block tile 128x128, BK=64, 8 warps (2m x 4n), warp tile 64x32.
// smem per stage: 4 matrices x 128 rows x 144B (64 bf16 + 16B pad) = 73728B; 2 stages.
// flags: 1 = accumulate Cin, 2 = leaky-relu epilogue
#define MAT_BYTES 18432
#define STG_BYTES 73728
#define GSMEM (2 * STG_BYTES)

__global__ void __launch_bounds__(256, 1)
k_mmagemm(const __nv_bfloat16* __restrict__ Ahi, const __nv_bfloat16* __restrict__ Alo,
          const __nv_bfloat16* __restrict__ Whi, const __nv_bfloat16* __restrict__ Wlo,
          const float* __restrict__ bias, const float* __restrict__ Cin,
          float* __restrict__ C, int Kp, int Nd, int flags)
{
    extern __shared__ char smc[];
    const uint32_t sbase = smem_u32(smc);
    const int tid = threadIdx.x;
    const int lane = tid & 31;
    const int wid = tid >> 5;
    const int wm = wid & 1;          // 0..1  (64 rows each)
    const int wn = wid >> 1;         // 0..3  (32 cols each)
    const int bm = blockIdx.y * 128;
    const int bn = blockIdx.x * 128;

    const __nv_bfloat16* gsrc[4] = {Ahi, Alo, Whi, Wlo};
    const int rbase[4] = {bm, bm, bn, bn};
    const int nc = Kp >> 6;

    // ldmatrix per-lane byte offsets within a matrix
    const uint32_t abyte = (uint32_t)((wm * 64 + (lane & 15)) * 144 + ((lane >> 4) & 1) * 16);
    const uint32_t bbyte = (uint32_t)((wn * 32 + (lane & 7)) * 144 + ((lane >> 3) & 1) * 16);

    float acc[4][4][4];
#pragma unroll
    for (int i = 0; i < 4; i++)
#pragma unroll
        for (int j = 0; j < 4; j++)
#pragma unroll
            for (int q = 0; q < 4; q++) acc[i][j][q] = 0.f;

    // ---- async load of one K-chunk into a stage ----
    auto load_chunk = [&](int c, int stage) {
        const int k0 = c * 64;
        const uint32_t sdst0 = sbase + (uint32_t)stage * STG_BYTES;
#pragma unroll
        for (int t = 0; t < 16; t++) {
            int idx = tid + t * 256;          // 0..4095
            int mat = idx >> 10;
            int u = idx & 1023;
            int row = u >> 3, seg = u & 7;
            uint32_t dst = sdst0 + (uint32_t)mat * MAT_BYTES + (uint32_t)(row * 144 + seg * 16);
            const __nv_bfloat16* src = gsrc[mat] + (size_t)(rbase[mat] + row) * Kp + k0 + seg * 8;
            cpasync16(dst, src);
        }
        asm volatile("cp.async.commit_group;" ::: "memory");
    };

    load_chunk(0, 0);

    for (int c = 0; c < nc; c++) {
        if (c + 1 < nc) {
            load_chunk(c + 1, (c + 1) & 1);
            asm volatile("cp.async.wait_group 1;" ::: "memory");
        } else {
            asm volatile("cp.async.wait_group 0;" ::: "memory");
        }
        __syncthreads();

        const uint32_t st = sbase + (uint32_t)(c & 1) * STG_BYTES;
        const uint32_t aHI = st + abyte;
        const uint32_t aLO = st + MAT_BYTES + abyte;
        const uint32_t wHI = st + 2 * MAT_BYTES + bbyte;
        const uint32_t wLO = st + 3 * MAT_BYTES + bbyte;

#pragma unroll
        for (int ks = 0; ks < 4; ks++) {
            uint32_t ah[4][4], al[4][4], wh[4][2], wl[4][2];
#pragma unroll
            for (int i = 0; i < 4; i++) {
                ldm_x4(ah[i], aHI + (uint32_t)(i * 2304 + ks * 32));
                ldm_x4(al[i], aLO + (uint32_t)(i * 2304 + ks * 32));
            }
#pragma unroll
            for (int j = 0; j < 4; j++) {
                ldm_x2(wh[j], wHI + (uint32_t)(j * 1152 + ks * 32));
                ldm_x2(wl[j], wLO + (uint32_t)(j * 1152 + ks * 32));
            }
#pragma unroll
            for (int i = 0; i < 4; i++)
#pragma unroll
                for (int j = 0; j < 4; j++) {
                    mma_bf16(acc[i][j], ah[i], wh[j]);
                    mma_bf16(acc[i][j], ah[i], wl[j]);
                    mma_bf16(acc[i][j], al[i], wh[j]);
                }
        }
        __syncthreads();
    }

    // ---- epilogue: registers -> global (float2 stores) ----
#pragma unroll
    for (int i = 0; i < 4; i++) {
        int row0 = bm + wm * 64 + i * 16 + (lane >> 2);
#pragma unroll
        for (int j = 0; j < 4; j++) {
            int col = bn + wn * 32 + j * 8 + ((lane & 3) << 1);
            if (col >= Nd) continue;
            float bx = 0.f, by = 0.f;
            if (bias) { float2 b = *(const float2*)(bias + col); bx = b.x; by = b.y; }
#pragma unroll
            for (int h = 0; h < 2; h++) {
                int row = row0 + h * 8;
                float v0 = acc[i][j][2 * h + 0] + bx;
                float v1 = acc[i][j][2 * h + 1] + by;
                size_t gi = (size_t)row * Nd + col;
                if (flags & 1) {
                    float2 ci = *(const float2*)(Cin + gi);
                    v0 += ci.x; v1 += ci.y;
                }
                if (flags & 2) {
                    v0 = (v0 >= 0.f) ? v0 : 0.01f * v0;
                    v1 = (v1 >= 0.f) ? v1 : 0.01f * v1;
                }
                *(float2*)(C + gi) = make_float2(v0, v1);
            }
        }
    }
}

// ---------------- graph-wise layernorm ----------------
__global__ void k_glnstats(const float* __restrict__ x, const int* __restrict__ sep, int D) {
    int s = blockIdx.x;
    int start = (s == 0) ? 0 : sep[s - 1];
    int end = sep[s];
    size_t total = (size_t)(end - start) * D;
    const float* base = &x[(size_t)start * D];
    float sum = 0.f, ss = 0.f;
    for (size_t i = threadIdx.x; i < total; i += blockDim.x) {
        float v = base[i];
        sum += v; ss += v * v;
    }
    __shared__ float s1[256], s2[256];
    int t = threadIdx.x;
    s1[t] = sum; s2[t] = ss;
    __syncthreads();
    for (int o = 128; o > 0; o >>= 1) {
        if (t < o) { s1[t] += s1[t + o]; s2[t] += s2[t + o]; }
        __syncthreads();
    }
    if (t == 0) {
        float cnt = (float)total;
        float mean = s1[0] / cnt;
        float var = s2[0] / cnt - mean * mean;
        g_glnstat[2 * s] = mean;
        g_glnstat[2 * s + 1] = rsqrtf(var + 1e-5f);
    }
}
__global__ void k_glnapply(float* __restrict__ x, const float* __restrict__ gamma,
                           const float* __restrict__ beta, int D) {
    int r = blockIdx.x;
    int f = blockIdx.y * blockDim.x + threadIdx.x;
    if (f >= D) return;
    int s = g_segid[r];
    size_t i = (size_t)r * D + f;
    x[i] = (x[i] - g_glnstat[2 * s]) * g_glnstat[2 * s + 1] * gamma[f] + beta[f];
}

// ---------------- edge aggregation ----------------
__global__ void k_scatter(const float* __restrict__ x, const int* __restrict__ src,
                          const int* __restrict__ dst, int D) {
    int e = blockIdx.x;
    int f4 = blockIdx.y * blockDim.x + threadIdx.x;
    if (f4 >= (D >> 2)) return;
    int s = src[e], d = dst[e];
    float4 v = *(const float4*)&x[(size_t)s * D + f4 * 4];
    atomicAdd((float4*)&g_agg[(size_t)d * D + f4 * 4], v);
}
__global__ void k_scale(int D) {
    int r = blockIdx.x;
    int f = blockIdx.y * blockDim.x + threadIdx.x;
    if (f < D) g_agg[(size_t)r * D + f] *= g_invdeg[r];
}

// ---------------- PairNorm ----------------
__global__ void k_pnstats(const float* __restrict__ x) {
    int r0 = blockIdx.x * 128;
    int t = threadIdx.x;
    float c1 = 0.f, c2 = 0.f, sq = 0.f;
    for (int r = 0; r < 128; r++) {
        const float* row = &x[(size_t)(r0 + r) * D_GH];
        float v1 = row[t], v2 = row[t + 256];
        c1 += v1; c2 += v2;
        sq += v1 * v1 + v2 * v2;
    }
    atomicAdd(&g_colsum[t], c1);
    atomicAdd(&g_colsum[t + 256], c2);
    __shared__ float sh[256];
    sh[t] = sq;
    __syncthreads();
    for (int o = 128; o > 0; o >>= 1) {
        if (t < o) sh[t] += sh[t + o];
        __syncthreads();
    }
    if (t == 0) atomicAdd(&g_scalar[0], sh[0]);
}
__global__ void k_pnfin() {
    int t = threadIdx.x;
    float m = g_colsum[t] / (float)NND;
    g_pnmean[t] = m;
    __shared__ float sh[512];
    sh[t] = m * m;
    __syncthreads();
    for (int o = 256; o > 0; o >>= 1) {
        if (t < o) sh[t] += sh[t + o];
        __syncthreads();
    }
    if (t == 0) {
        float var = g_scalar[0] / (float)NND - sh[0];
        g_scalar[1] = 1.f / (1e-5f + sqrtf(fmaxf(var, 0.f)));
    }
}
__global__ void k_pnapply(const float* __restrict__ in, float* __restrict__ out) {
    size_t i = (size_t)blockIdx.x * blockDim.x + threadIdx.x;
    if (i >= (size_t)NND * D_GH) return;
    int f = (int)(i & (D_GH - 1));
    float v = (in[i] - g_pnmean[f]) * g_scalar[1];
    out[i] = fmaxf(v, 0.f);
}

// ---------------- final pooling + linear ----------------
__global__ void k_finaldot(const float* __restrict__ x, const float* __restrict__ wc) {
    int gt = blockIdx.x * blockDim.x + threadIdx.x;
    int node = gt >> 5;
    int lane = gt & 31;
    if (node >= NND) return;
    const float* row = &x[(size_t)node * D_GH];
    float s = 0.f;
#pragma unroll
    for (int k = 0; k < 16; k++) s += row[k * 32 + lane] * wc[k * 32 + lane];
#pragma unroll
    for (int o = 16; o > 0; o >>= 1) s += __shfl_xor_sync(0xFFFFFFFFu, s, o);
    if (lane == 0) atomicAdd(&g_segout[g_segid[node]], s);
}
__global__ void k_out(float* __restrict__ out, const float* __restrict__ bc) {
    int t = threadIdx.x;
    if (t < NS) out[t] = g_segout[t] + bc[0];
}

// ---------------- host orchestration ----------------
static __nv_bfloat16 *h_ahi, *h_alo, *h_whi, *h_wlo;

static inline void tc_gemm(const float* A, const float* W, const float* bias,
                           const float* Cin, float* C, int M, int K, int Nd, int flags) {
    int Kp = (K + 63) & ~63;
    int Ndp = (Nd + 127) & ~127;
    k_cvtA<<<(M * Kp + 255) / 256, 256>>>(A, h_ahi, h_alo, M, K, Kp);
    k_cvtW<<<(Ndp * Kp + 255) / 256, 256>>>(W, h_whi, h_wlo, Nd, K, Ndp, Kp);
    dim3 grid(Ndp / 128, M / 128);
    k_mmagemm<<<grid, 256, GSMEM>>>(h_ahi, h_alo, h_whi, h_wlo, bias, Cin, C, Kp, Nd, flags);
}

extern "C" void kernel_launch(void* const* d_in, const int* in_sizes, int n_in,
                              void* d_out, int out_size) {
    const float* nf   = (const float*)d_in[0];
    const float* ncf  = (const float*)d_in[1];
    const float* emb  = (const float*)d_in[2];
    const float* w1   = (const float*)d_in[3];
    const float* b1   = (const float*)d_in[4];
    const float* g1   = (const float*)d_in[5];
    const float* be1  = (const float*)d_in[6];
    const float* w2   = (const float*)d_in[7];
    const float* b2   = (const float*)d_in[8];
    const float* g2   = (const float*)d_in[9];
    const float* be2  = (const float*)d_in[10];
    const float* wl1  = (const float*)d_in[11];
    const float* bl1  = (const float*)d_in[12];
    const float* wr1  = (const float*)d_in[13];
    const float* wl2  = (const float*)d_in[14];
    const float* bl2  = (const float*)d_in[15];
    const float* wr2  = (const float*)d_in[16];
    const float* wl3  = (const float*)d_in[17];
    const float* bl3  = (const float*)d_in[18];
    const float* wr3  = (const float*)d_in[19];
    const float* wc   = (const float*)d_in[20];
    const float* bc   = (const float*)d_in[21];
    const int* ops    = (const int*)d_in[22];
    const int* edges  = (const int*)d_in[23];
    const int* sep    = (const int*)d_in[24];
    float* out        = (float*)d_out;

    const int* src = edges;
    const int* dst = edges + NE;

    cudaFuncSetAttribute(k_mmagemm, cudaFuncAttributeMaxDynamicSharedMemorySize, GSMEM);

    void *p_agg, *p_colsum, *p_scalar, *p_segout, *p_x0, *p_x1, *p_x2, *p_xa, *p_xb;
    void *p_ahi, *p_alo, *p_whi, *p_wlo;
    cudaGetSymbolAddress(&p_agg, g_agg);
    cudaGetSymbolAddress(&p_colsum, g_colsum);
    cudaGetSymbolAddress(&p_scalar, g_scalar);
    cudaGetSymbolAddress(&p_segout, g_segout);
    cudaGetSymbolAddress(&p_x0, g_x0);
    cudaGetSymbolAddress(&p_x1, g_x1);
    cudaGetSymbolAddress(&p_x2, g_x2);
    cudaGetSymbolAddress(&p_xa, g_xa);
    cudaGetSymbolAddress(&p_xb, g_xb);
    cudaGetSymbolAddress(&p_ahi, g_ahi);
    cudaGetSymbolAddress(&p_alo, g_alo);
    cudaGetSymbolAddress(&p_whi, g_whi);
    cudaGetSymbolAddress(&p_wlo, g_wlo);
    float* d_agg = (float*)p_agg;
    float* d_x0 = (float*)p_x0;
    float* d_x1 = (float*)p_x1;
    float* d_x2 = (float*)p_x2;
    float* d_xa = (float*)p_xa;
    float* d_xb = (float*)p_xb;
    h_ahi = (__nv_bfloat16*)p_ahi;
    h_alo = (__nv_bfloat16*)p_alo;
    h_whi = (__nv_bfloat16*)p_whi;
    h_wlo = (__nv_bfloat16*)p_wlo;

    // ---- prep ----
    k_segid<<<(NND + 255) / 256, 256>>>(sep);
    k_deg<<<(NE + 255) / 256, 256>>>(dst);
    k_invdeg<<<(NND + 255) / 256, 256>>>();
    {
        size_t n = (size_t)NND * D_0;
        k_concat<<<(unsigned)((n + 255) / 256), 256>>>(nf, ncf, emb, ops);
    }

    // ---- MLP layer 1 ----
    tc_gemm(d_x0, w1, b1, nullptr, d_x1, NND, D_0, D_X, /*leaky*/2);
    k_glnstats<<<NS, 256>>>(d_x1, sep, D_X);
    k_glnapply<<<dim3(NND, (D_X + 255) / 256), 256>>>(d_x1, g1, be1, D_X);

    // ---- MLP layer 2 ----
    tc_gemm(d_x1, w2, b2, nullptr, d_x2, NND, D_X, D_GIN, 2);
    k_glnstats<<<NS, 256>>>(d_x2, sep, D_GIN);
    k_glnapply<<<dim3(NND, (D_GIN + 255) / 256), 256>>>(d_x2, g2, be2, D_GIN);

    // ---- SAGE layer 1 (K = 256) ----
    {
        size_t n = (size_t)NND * D_GIN;
        k_zero<<<(unsigned)((n + 255) / 256), 256>>>(d_agg, n);
        k_scatter<<<dim3(NE, 1), 64>>>(d_x2, src, dst, D_GIN);
        k_scale<<<dim3(NND, 1), 256>>>(D_GIN);
        tc_gemm(d_agg, wl1, bl1, nullptr, d_xb, NND, D_GIN, D_GH, 0);
        tc_gemm(d_x2, wr1, nullptr, d_xb, d_xb, NND, D_GIN, D_GH, 1);
        k_zero<<<3, 256>>>((float*)p_colsum, D_GH);
        k_zero<<<1, 2>>>((float*)p_scalar, 2);
        k_pnstats<<<NND / 128, 256>>>(d_xb);
        k_pnfin<<<1, 512>>>();
        size_t m = (size_t)NND * D_GH;
        k_pnapply<<<(unsigned)((m + 255) / 256), 256>>>(d_xb, d_xa);
    }

    // ---- SAGE layer 2 (K = 512) ----
    {
        size_t n = (size_t)NND * D_GH;
        k_zero<<<(unsigned)((n + 255) / 256), 256>>>(d_agg, n);
        k_scatter<<<dim3(NE, 1), 128>>>(d_xa, src, dst, D_GH);
        k_scale<<<dim3(NND, 2), 256>>>(D_GH);
        tc_gemm(d_agg, wl2, bl2, nullptr, d_xb, NND, D_GH, D_GH, 0);
        tc_gemm(d_xa, wr2, nullptr, d_xb, d_xb, NND, D_GH, D_GH, 1);
        k_zero<<<3, 256>>>((float*)p_colsum, D_GH);
        k_zero<<<1, 2>>>((float*)p_scalar, 2);
        k_pnstats<<<NND / 128, 256>>>(d_xb);
        k_pnfin<<<1, 512>>>();
        k_pnapply<<<(unsigned)((n + 255) / 256), 256>>>(d_xb, d_xa);
    }

    // ---- SAGE layer 3 (K = 512, no pairnorm/relu) ----
    {
        size_t n = (size_t)NND * D_GH;
        k_zero<<<(unsigned)((n + 255) / 256), 256>>>(d_agg, n);
        k_scatter<<<dim3(NE, 1), 128>>>(d_xa, src, dst, D_GH);
        k_scale<<<dim3(NND, 2), 256>>>(D_GH);
        tc_gemm(d_agg, wl3, bl3, nullptr, d_xb, NND, D_GH, D_GH, 0);
        tc_gemm(d_xa, wr3, nullptr, d_xb, d_xb, NND, D_GH, D_GH, 1);
    }

    // ---- segment pooling + final linear ----
    k_zero<<<1, NS>>>((float*)p_segout, NS);
    k_finaldot<<<(NND * 32) / 256, 256>>>(d_xb, wc);
    k_out<<<1, NS>>>(out, bc);
}

// round 6
// speedup vs baseline: 2.2008x; 1.0086x over previous
#include <cuda_runtime.h>
#include <cuda_bf16.h>
#include <math.h>
#include <stdint.h>

// ---------------- problem constants ----------------
#define NND 32768
#define NE  262144
#define NS  128
#define D_0 190
#define D_X 380
#define D_GIN 256
#define D_GH 512

// ---------------- device scratch (static, no allocation) ----------------
__device__ __align__(128) float g_x1[(size_t)NND * D_X];
__device__ __align__(128) float g_x2[(size_t)NND * D_GIN];
__device__ __align__(128) float g_xa[(size_t)NND * D_GH];
__device__ __align__(128) float g_xb[(size_t)NND * D_GH];
__device__ __align__(128) float g_agg[(size_t)NND * D_GH];
__device__ __align__(128) __nv_bfloat16 g_ahi[(size_t)NND * 1024];
__device__ __align__(128) __nv_bfloat16 g_alo[(size_t)NND * 1024];
__device__ __align__(128) __nv_bfloat16 g_whi[512 * 1024];
__device__ __align__(128) __nv_bfloat16 g_wlo[512 * 1024];
__device__ float g_invdeg[NND];
__device__ int   g_segid[NND];
__device__ float g_glnstat[NS * 2];
__device__ float g_colsum[D_GH];
__device__ float g_pnmean[D_GH];
__device__ float g_scalar[2];
__device__ float g_segout[NS];

// ---------------- PTX helpers (compute_103-safe) ----------------
__device__ __forceinline__ uint32_t smem_u32(const void* p) {
    uint32_t a;
    asm("{ .reg .u64 t; cvta.to.shared.u64 t, %1; cvt.u32.u64 %0, t; }" : "=r"(a) : "l"(p));
    return a;
}
__device__ __forceinline__ void cpasync16(uint32_t dst, const void* src) {
    asm volatile("cp.async.cg.shared.global [%0], [%1], 16;" :: "r"(dst), "l"(src) : "memory");
}
__device__ __forceinline__ void ldm_x4(uint32_t* r, uint32_t addr) {
    asm volatile("ldmatrix.sync.aligned.m8n8.x4.shared.b16 {%0,%1,%2,%3},[%4];"
                 : "=r"(r[0]), "=r"(r[1]), "=r"(r[2]), "=r"(r[3]) : "r"(addr));
}
__device__ __forceinline__ void ldm_x2(uint32_t* r, uint32_t addr) {
    asm volatile("ldmatrix.sync.aligned.m8n8.x2.shared.b16 {%0,%1},[%2];"
                 : "=r"(r[0]), "=r"(r[1]) : "r"(addr));
}
__device__ __forceinline__ void mma_bf16(float* d, const uint32_t* a, const uint32_t* b) {
    asm volatile(
        "mma.sync.aligned.m16n8k16.row.col.f32.bf16.bf16.f32 "
        "{%0,%1,%2,%3}, {%4,%5,%6,%7}, {%8,%9}, {%0,%1,%2,%3};"
        : "+f"(d[0]), "+f"(d[1]), "+f"(d[2]), "+f"(d[3])
        : "r"(a[0]), "r"(a[1]), "r"(a[2]), "r"(a[3]), "r"(b[0]), "r"(b[1]));
}
__device__ __forceinline__ void split_bf16(float v, __nv_bfloat16& h, __nv_bfloat16& l) {
    h = __float2bfloat16(v);
    l = __float2bfloat16(v - __bfloat162float(h));
}

// ---------------- small utility kernels ----------------
__global__ void k_zero(float* p, size_t n) {
    size_t i = (size_t)blockIdx.x * blockDim.x + threadIdx.x;
    if (i < n) p[i] = 0.f;
}
__global__ void k_segid(const int* __restrict__ sep) {
    int i = blockIdx.x * blockDim.x + threadIdx.x;
    if (i >= NND) return;
    int lo = 0, hi = NS;
    while (lo < hi) { int mid = (lo + hi) >> 1; if (sep[mid] <= i) lo = mid + 1; else hi = mid; }
    g_segid[i] = lo;
    g_invdeg[i] = 0.f;
}
__global__ void k_deg(const int* __restrict__ dst) {
    int e = blockIdx.x * blockDim.x + threadIdx.x;
    if (e < NE) atomicAdd(&g_invdeg[dst[e]], 1.f);
}
__global__ void k_invdeg() {
    int i = blockIdx.x * blockDim.x + threadIdx.x;
    if (i < NND) g_invdeg[i] = 1.f / fmaxf(g_invdeg[i], 1.f);
}
// concat -> bf16 hi/lo directly (stride 192, cols 190-191 zero)
__global__ void k_concat_cvt(const float* __restrict__ nf, const float* __restrict__ ncf,
                             const float* __restrict__ emb, const int* __restrict__ ops,
                             __nv_bfloat16* __restrict__ hi, __nv_bfloat16* __restrict__ lo) {
    size_t i = (size_t)blockIdx.x * blockDim.x + threadIdx.x;
    if (i >= (size_t)NND * 192) return;
    int r = (int)(i / 192);
    int c = (int)(i - (size_t)r * 192);
    float v = 0.f;
    if (c < 90)       v = nf[(size_t)r * 90 + c];
    else if (c < 126) v = ncf[(size_t)r * 36 + (c - 90)];
    else if (c < 190) v = emb[(size_t)ops[r] * 64 + (c - 126)];
    __nv_bfloat16 h, l;
    split_bf16(v, h, l);
    hi[i] = h; lo[i] = l;
}
// single-weight convert with padding, row stride Kp
__global__ void k_cvtW(const float* __restrict__ W, __nv_bfloat16* __restrict__ hi,
                       __nv_bfloat16* __restrict__ lo, int Nd, int K, int Ndp, int Kp) {
    int idx = blockIdx.x * blockDim.x + threadIdx.x;
    if (idx >= Ndp * Kp) return;
    int n = idx / Kp, k = idx - n * Kp;
    float v = (n < Nd && k < K) ? W[(size_t)n * K + k] : 0.f;
    __nv_bfloat16 h, l;
    split_bf16(v, h, l);
    hi[idx] = h; lo[idx] = l;
}
// paired weight convert: [wl | wr], both 512 x K1, output stride 2*K1
__global__ void k_cvtWpair(const float* __restrict__ wl, const float* __restrict__ wr,
                           __nv_bfloat16* __restrict__ hi, __nv_bfloat16* __restrict__ lo, int K1) {
    int Kt = 2 * K1;
    int idx = blockIdx.x * blockDim.x + threadIdx.x;
    if (idx >= 512 * Kt) return;
    int n = idx / Kt, k = idx - n * Kt;
    float v = (k < K1) ? wl[(size_t)n * K1 + k] : wr[(size_t)n * K1 + (k - K1)];
    __nv_bfloat16 h, l;
    split_bf16(v, h, l);
    hi[idx] = h; lo[idx] = l;
}

// ---------------- mma.sync bf16x3 GEMM ----------------
// block tile 128x128, BK=64, 8 warps (2m x 4n), warp tile 64x32.
// flags: 2 = leaky-relu, 4 = fused segment-dot epilogue (no C store)
#define MAT_BYTES 18432
#define STG_BYTES 73728
#define GSMEM (2 * STG_BYTES)

__global__ void __launch_bounds__(256, 1)
k_mmagemm(const __nv_bfloat16* __restrict__ Ahi, const __nv_bfloat16* __restrict__ Alo,
          const __nv_bfloat16* __restrict__ Whi, const __nv_bfloat16* __restrict__ Wlo,
          const float* __restrict__ bias, float* __restrict__ C,
          const float* __restrict__ wc, int Kp, int Nd, int flags)
{
    extern __shared__ char smc[];
    const uint32_t sbase = smem_u32(smc);
    const int tid = threadIdx.x;
    const int lane = tid & 31;
    const int wid = tid >> 5;
    const int wm = wid & 1;
    const int wn = wid >> 1;
    const int bm = blockIdx.y * 128;
    const int bn = blockIdx.x * 128;

    const __nv_bfloat16* gsrc[4] = {Ahi, Alo, Whi, Wlo};
    const int rbase[4] = {bm, bm, bn, bn};
    const int nc = Kp >> 6;

    const uint32_t abyte = (uint32_t)((wm * 64 + (lane & 15)) * 144 + ((lane >> 4) & 1) * 16);
    const uint32_t bbyte = (uint32_t)((wn * 32 + (lane & 7)) * 144 + ((lane >> 3) & 1) * 16);

    float acc[4][4][4];
#pragma unroll
    for (int i = 0; i < 4; i++)
#pragma unroll
        for (int j = 0; j < 4; j++)
#pragma unroll
            for (int q = 0; q < 4; q++) acc[i][j][q] = 0.f;

    auto load_chunk = [&](int c, int stage) {
        const int k0 = c * 64;
        const uint32_t sdst0 = sbase + (uint32_t)stage * STG_BYTES;
#pragma unroll
        for (int t = 0; t < 16; t++) {
            int idx = tid + t * 256;
            int mat = idx >> 10;
            int u = idx & 1023;
            int row = u >> 3, seg = u & 7;
            uint32_t dst = sdst0 + (uint32_t)mat * MAT_BYTES + (uint32_t)(row * 144 + seg * 16);
            const __nv_bfloat16* src = gsrc[mat] + (size_t)(rbase[mat] + row) * Kp + k0 + seg * 8;
            cpasync16(dst, src);
        }
        asm volatile("cp.async.commit_group;" ::: "memory");
    };

    load_chunk(0, 0);

    for (int c = 0; c < nc; c++) {
        if (c + 1 < nc) {
            load_chunk(c + 1, (c + 1) & 1);
            asm volatile("cp.async.wait_group 1;" ::: "memory");
        } else {
            asm volatile("cp.async.wait_group 0;" ::: "memory");
        }
        __syncthreads();

        const uint32_t st = sbase + (uint32_t)(c & 1) * STG_BYTES;
        const uint32_t aHI = st + abyte;
        const uint32_t aLO = st + MAT_BYTES + abyte;
        const uint32_t wHI = st + 2 * MAT_BYTES + bbyte;
        const uint32_t wLO = st + 3 * MAT_BYTES + bbyte;

#pragma unroll
        for (int ks = 0; ks < 4; ks++) {
            uint32_t ah[4][4], al[4][4], wh[4][2], wl[4][2];
#pragma unroll
            for (int i = 0; i < 4; i++) {
                ldm_x4(ah[i], aHI + (uint32_t)(i * 2304 + ks * 32));
                ldm_x4(al[i], aLO + (uint32_t)(i * 2304 + ks * 32));
            }
#pragma unroll
            for (int j = 0; j < 4; j++) {
                ldm_x2(wh[j], wHI + (uint32_t)(j * 1152 + ks * 32));
                ldm_x2(wl[j], wLO + (uint32_t)(j * 1152 + ks * 32));
            }
#pragma unroll
            for (int i = 0; i < 4; i++)
#pragma unroll
                for (int j = 0; j < 4; j++) {
                    mma_bf16(acc[i][j], ah[i], wh[j]);
                    mma_bf16(acc[i][j], ah[i], wl[j]);
                    mma_bf16(acc[i][j], al[i], wh[j]);
                }
        }
        __syncthreads();
    }

    if (!(flags & 4)) {
        // ---- normal epilogue: registers -> global (float2 stores) ----
#pragma unroll
        for (int i = 0; i < 4; i++) {
            int row0 = bm + wm * 64 + i * 16 + (lane >> 2);
#pragma unroll
            for (int j = 0; j < 4; j++) {
                int col = bn + wn * 32 + j * 8 + ((lane & 3) << 1);
                if (col >= Nd) continue;
                float bx = 0.f, by = 0.f;
                if (bias) { float2 b = *(const float2*)(bias + col); bx = b.x; by = b.y; }
#pragma unroll
                for (int h = 0; h < 2; h++) {
                    int row = row0 + h * 8;
                    float v0 = acc[i][j][2 * h + 0] + bx;
                    float v1 = acc[i][j][2 * h + 1] + by;
                    if (flags & 2) {
                        v0 = (v0 >= 0.f) ? v0 : 0.01f * v0;
                        v1 = (v1 >= 0.f) ? v1 : 0.01f * v1;
                    }
                    *(float2*)(C + (size_t)row * Nd + col) = make_float2(v0, v1);
                }
            }
        }
    } else {
        // ---- fused final-dot epilogue: per-row dot with wc -> segout atomics ----
        float part[4][2];
#pragma unroll
        for (int i = 0; i < 4; i++) { part[i][0] = 0.f; part[i][1] = 0.f; }
#pragma unroll
        for (int i = 0; i < 4; i++) {
#pragma unroll
            for (int j = 0; j < 4; j++) {
                int col = bn + wn * 32 + j * 8 + ((lane & 3) << 1);
                if (col >= Nd) continue;
                float2 w = *(const float2*)(wc + col);
                float bx = 0.f, by = 0.f;
                if (bias) { float2 b = *(const float2*)(bias + col); bx = b.x; by = b.y; }
#pragma unroll
                for (int h = 0; h < 2; h++) {
                    float v0 = acc[i][j][2 * h + 0] + bx;
                    float v1 = acc[i][j][2 * h + 1] + by;
                    part[i][h] += v0 * w.x + v1 * w.y;
                }
            }
        }
#pragma unroll
        for (int i = 0; i < 4; i++)
#pragma unroll
            for (int h = 0; h < 2; h++) {
                float p = part[i][h];
                p += __shfl_xor_sync(0xFFFFFFFFu, p, 1);
                p += __shfl_xor_sync(0xFFFFFFFFu, p, 2);
                if ((lane & 3) == 0) {
                    int row = bm + wm * 64 + i * 16 + h * 8 + (lane >> 2);
                    atomicAdd(&g_segout[g_segid[row]], p);
                }
            }
    }
}

// ---------------- graph-wise layernorm ----------------
__global__ void k_glnstats(const float* __restrict__ x, const int* __restrict__ sep, int D) {
    int s = blockIdx.x;
    int start = (s == 0) ? 0 : sep[s - 1];
    int end = sep[s];
    size_t total = (size_t)(end - start) * D;
    const float* base = &x[(size_t)start * D];
    float sum = 0.f, ss = 0.f;
    for (size_t i = threadIdx.x; i < total; i += blockDim.x) {
        float v = base[i];
        sum += v; ss += v * v;
    }
    __shared__ float s1[256], s2[256];
    int t = threadIdx.x;
    s1[t] = sum; s2[t] = ss;
    __syncthreads();
    for (int o = 128; o > 0; o >>= 1) {
        if (t < o) { s1[t] += s1[t + o]; s2[t] += s2[t + o]; }
        __syncthreads();
    }
    if (t == 0) {
        float cnt = (float)total;
        float mean = s1[0] / cnt;
        float var = s2[0] / cnt - mean * mean;
        g_glnstat[2 * s] = mean;
        g_glnstat[2 * s + 1] = rsqrtf(var + 1e-5f);
    }
}
// gln apply + bf16 split write; optional fp32 in-place write. pads [D, Kpad) with zeros.
__global__ void k_glnapply_cvt(float* __restrict__ x, const float* __restrict__ gamma,
                               const float* __restrict__ beta, int D, int Kpad,
                               int colOff, int strideK,
                               __nv_bfloat16* __restrict__ hi, __nv_bfloat16* __restrict__ lo,
                               int writeF32) {
    int r = blockIdx.x;
    int f = blockIdx.y * blockDim.x + threadIdx.x;
    if (f >= Kpad) return;
    float v = 0.f;
    if (f < D) {
        int s = g_segid[r];
        size_t i = (size_t)r * D + f;
        v = (x[i] - g_glnstat[2 * s]) * g_glnstat[2 * s + 1] * gamma[f] + beta[f];
        if (writeF32) x[i] = v;
    }
    __nv_bfloat16 h, l;
    split_bf16(v, h, l);
    size_t o = (size_t)r * strideK + colOff + f;
    hi[o] = h; lo[o] = l;
}

// ---------------- edge aggregation ----------------
__global__ void k_scatter(const float* __restrict__ x, const int* __restrict__ src,
                          const int* __restrict__ dst, int D) {
    int e = blockIdx.x;
    int f4 = blockIdx.y * blockDim.x + threadIdx.x;
    if (f4 >= (D >> 2)) return;
    int s = src[e], d = dst[e];
    float4 v = *(const float4*)&x[(size_t)s * D + f4 * 4];
    atomicAdd((float4*)&g_agg[(size_t)d * D + f4 * 4], v);
}
// scale by invdeg + bf16 split into combined A buffer at column 0
__global__ void k_scale_cvt(int D, int strideK,
                            __nv_bfloat16* __restrict__ hi, __nv_bfloat16* __restrict__ lo) {
    int r = blockIdx.x;
    int f = blockIdx.y * blockDim.x + threadIdx.x;
    if (f >= D) return;
    float v = g_agg[(size_t)r * D + f] * g_invdeg[r];
    __nv_bfloat16 h, l;
    split_bf16(v, h, l);
    size_t o = (size_t)r * strideK + f;
    hi[o] = h; lo[o] = l;
}

// ---------------- PairNorm ----------------
__global__ void k_pnstats(const float* __restrict__ x) {
    int r0 = blockIdx.x * 128;
    int t = threadIdx.x;
    float c1 = 0.f, c2 = 0.f, sq = 0.f;
    for (int r = 0; r < 128; r++) {
        const float* row = &x[(size_t)(r0 + r) * D_GH];
        float v1 = row[t], v2 = row[t + 256];
        c1 += v1; c2 += v2;
        sq += v1 * v1 + v2 * v2;
    }
    atomicAdd(&g_colsum[t], c1);
    atomicAdd(&g_colsum[t + 256], c2);
    __shared__ float sh[256];
    sh[t] = sq;
    __syncthreads();
    for (int o = 128; o > 0; o >>= 1) {
        if (t < o) sh[t] += sh[t + o];
        __syncthreads();
    }
    if (t == 0) atomicAdd(&g_scalar[0], sh[0]);
}
__global__ void k_pnfin() {
    int t = threadIdx.x;
    float m = g_colsum[t] / (float)NND;
    g_pnmean[t] = m;
    __shared__ float sh[512];
    sh[t] = m * m;
    __syncthreads();
    for (int o = 256; o > 0; o >>= 1) {
        if (t < o) sh[t] += sh[t + o];
        __syncthreads();
    }
    if (t == 0) {
        float var = g_scalar[0] / (float)NND - sh[0];
        g_scalar[1] = 1.f / (1e-5f + sqrtf(fmaxf(var, 0.f)));
    }
}
// pairnorm apply + relu -> xa fp32 AND bf16 hi/lo at column 512 of K=1024 buffer
__global__ void k_pnapply_cvt(const float* __restrict__ in, float* __restrict__ out,
                              __nv_bfloat16* __restrict__ hi, __nv_bfloat16* __restrict__ lo) {
    size_t i = (size_t)blockIdx.x * blockDim.x + threadIdx.x;
    if (i >= (size_t)NND * D_GH) return;
    int f = (int)(i & (D_GH - 1));
    int r = (int)(i >> 9);
    float v = (in[i] - g_pnmean[f]) * g_scalar[1];
    v = fmaxf(v, 0.f);
    out[i] = v;
    __nv_bfloat16 h, l;
    split_bf16(v, h, l);
    size_t o = (size_t)r * 1024 + 512 + f;
    hi[o] = h; lo[o] = l;
}

__global__ void k_out(float* __restrict__ out, const float* __restrict__ bc) {
    int t = threadIdx.x;
    if (t < NS) out[t] = g_segout[t] + bc[0];
}

// ---------------- host orchestration ----------------
static __nv_bfloat16 *h_ahi, *h_alo, *h_whi, *h_wlo;

static inline void run_gemm(const float* bias, float* C, const float* wc,
                            int Kp, int Nd, int Ndp, int flags) {
    dim3 grid(Ndp / 128, NND / 128);
    k_mmagemm<<<grid, 256, GSMEM>>>(h_ahi, h_alo, h_whi, h_wlo, bias, C, wc, Kp, Nd, flags);
}

extern "C" void kernel_launch(void* const* d_in, const int* in_sizes, int n_in,
                              void* d_out, int out_size) {
    const float* nf   = (const float*)d_in[0];
    const float* ncf  = (const float*)d_in[1];
    const float* emb  = (const float*)d_in[2];
    const float* w1   = (const float*)d_in[3];
    const float* b1   = (const float*)d_in[4];
    const float* g1   = (const float*)d_in[5];
    const float* be1  = (const float*)d_in[6];
    const float* w2   = (const float*)d_in[7];
    const float* b2   = (const float*)d_in[8];
    const float* g2   = (const float*)d_in[9];
    const float* be2  = (const float*)d_in[10];
    const float* wl1  = (const float*)d_in[11];
    const float* bl1  = (const float*)d_in[12];
    const float* wr1  = (const float*)d_in[13];
    const float* wl2  = (const float*)d_in[14];
    const float* bl2  = (const float*)d_in[15];
    const float* wr2  = (const float*)d_in[16];
    const float* wl3  = (const float*)d_in[17];
    const float* bl3  = (const float*)d_in[18];
    const float* wr3  = (const float*)d_in[19];
    const float* wc   = (const float*)d_in[20];
    const float* bc   = (const float*)d_in[21];
    const int* ops    = (const int*)d_in[22];
    const int* edges  = (const int*)d_in[23];
    const int* sep    = (const int*)d_in[24];
    float* out        = (float*)d_out;

    const int* src = edges;
    const int* dst = edges + NE;

    cudaFuncSetAttribute(k_mmagemm, cudaFuncAttributeMaxDynamicSharedMemorySize, GSMEM);

    void *p_agg, *p_colsum, *p_scalar, *p_segout, *p_x1, *p_x2, *p_xa, *p_xb;
    void *p_ahi, *p_alo, *p_whi, *p_wlo;
    cudaGetSymbolAddress(&p_agg, g_agg);
    cudaGetSymbolAddress(&p_colsum, g_colsum);
    cudaGetSymbolAddress(&p_scalar, g_scalar);
    cudaGetSymbolAddress(&p_segout, g_segout);
    cudaGetSymbolAddress(&p_x1, g_x1);
    cudaGetSymbolAddress(&p_x2, g_x2);
    cudaGetSymbolAddress(&p_xa, g_xa);
    cudaGetSymbolAddress(&p_xb, g_xb);
    cudaGetSymbolAddress(&p_ahi, g_ahi);
    cudaGetSymbolAddress(&p_alo, g_alo);
    cudaGetSymbolAddress(&p_whi, g_whi);
    cudaGetSymbolAddress(&p_wlo, g_wlo);
    float* d_agg = (float*)p_agg;
    float* d_x1 = (float*)p_x1;
    float* d_x2 = (float*)p_x2;
    float* d_xa = (float*)p_xa;
    float* d_xb = (float*)p_xb;
    h_ahi = (__nv_bfloat16*)p_ahi;
    h_alo = (__nv_bfloat16*)p_alo;
    h_whi = (__nv_bfloat16*)p_whi;
    h_wlo = (__nv_bfloat16*)p_wlo;

    // ---- prep ----
    k_segid<<<(NND + 255) / 256, 256>>>(sep);
    k_deg<<<(NE + 255) / 256, 256>>>(dst);
    k_invdeg<<<(NND + 255) / 256, 256>>>();
    k_concat_cvt<<<(NND * 192 + 255) / 256, 256>>>(nf, ncf, emb, ops, h_ahi, h_alo);

    // ---- MLP layer 1: K=192 (190 padded), Nd=380 (Ndp 384) ----
    k_cvtW<<<(384 * 192 + 255) / 256, 256>>>(w1, h_whi, h_wlo, D_X, D_0, 384, 192);
    run_gemm(b1, d_x1, nullptr, 192, D_X, 384, /*leaky*/2);
    k_glnstats<<<NS, 256>>>(d_x1, sep, D_X);
    // normalized x1 -> bf16 hi/lo, stride 384 (K for MLP2), no fp32 needed
    k_glnapply_cvt<<<dim3(NND, 2), 256>>>(d_x1, g1, be1, D_X, 384, 0, 384, h_ahi, h_alo, 0);

    // ---- MLP layer 2: K=384 (380 padded), Nd=256 ----
    k_cvtW<<<(256 * 384 + 255) / 256, 256>>>(w2, h_whi, h_wlo, D_GIN, D_X, 256, 384);
    run_gemm(b2, d_x2, nullptr, 384, D_GIN, 256, 2);
    k_glnstats<<<NS, 256>>>(d_x2, sep, D_GIN);
    // normalized x2: fp32 in-place (for scatter) + bf16 at cols [256,512) of K=512 buffer
    k_glnapply_cvt<<<dim3(NND, 1), 256>>>(d_x2, g2, be2, D_GIN, 256, 256, 512, h_ahi, h_alo, 1);

    // ---- SAGE layer 1: combined K=512 ([agg256 | x256] @ [wl1 | wr1]) ----
    {
        size_t n = (size_t)NND * D_GIN;
        k_zero<<<(unsigned)((n + 255) / 256), 256>>>(d_agg, n);
        k_scatter<<<dim3(NE, 1), 64>>>(d_x2, src, dst, D_GIN);
        k_cvtWpair<<<(512 * 512 + 255) / 256, 256>>>(wl1, wr1, h_whi, h_wlo, D_GIN);
        k_scale_cvt<<<dim3(NND, 1), 256>>>(D_GIN, 512, h_ahi, h_alo);
        run_gemm(bl1, d_xb, nullptr, 512, D_GH, 512, 0);
        k_zero<<<3, 256>>>((float*)p_colsum, D_GH);
        k_zero<<<1, 2>>>((float*)p_scalar, 2);
        k_pnstats<<<NND / 128, 256>>>(d_xb);
        k_pnfin<<<1, 512>>>();
        size_t m = (size_t)NND * D_GH;
        k_pnapply_cvt<<<(unsigned)((m + 255) / 256), 256>>>(d_xb, d_xa, h_ahi, h_alo);
    }

    // ---- SAGE layer 2: combined K=1024 ----
    {
        size_t n = (size_t)NND * D_GH;
        k_zero<<<(unsigned)((n + 255) / 256), 256>>>(d_agg, n);
        k_scatter<<<dim3(NE, 1), 128>>>(d_xa, src, dst, D_GH);
        k_cvtWpair<<<(512 * 1024 + 255) / 256, 256>>>(wl2, wr2, h_whi, h_wlo, D_GH);
        k_scale_cvt<<<dim3(NND, 2), 256>>>(D_GH, 1024, h_ahi, h_alo);
        run_gemm(bl2, d_xb, nullptr, 1024, D_GH, 512, 0);
        k_zero<<<3, 256>>>((float*)p_colsum, D_GH);
        k_zero<<<1, 2>>>((float*)p_scalar, 2);
        k_pnstats<<<NND / 128, 256>>>(d_xb);
        k_pnfin<<<1, 512>>>();
        k_pnapply_cvt<<<(unsigned)((n + 255) / 256), 256>>>(d_xb, d_xa, h_ahi, h_alo);
    }

    // ---- SAGE layer 3: combined K=1024, fused final dot ----
    {
        size_t n = (size_t)NND * D_GH;
        k_zero<<<(unsigned)((n + 255) / 256), 256>>>(d_agg, n);
        k_scatter<<<dim3(NE, 1), 128>>>(d_xa, src, dst, D_GH);
        k_cvtWpair<<<(512 * 1024 + 255) / 256, 256>>>(wl3, wr3, h_whi, h_wlo, D_GH);
        k_scale_cvt<<<dim3(NND, 2), 256>>>(D_GH, 1024, h_ahi, h_alo);
        k_zero<<<1, NS>>>((float*)p_segout, NS);
        run_gemm(bl3, d_xb, wc, 1024, D_GH, 512, /*fused dot*/4);
    }

    k_out<<<1, NS>>>(out, bc);
}

// round 8
// speedup vs baseline: 2.6742x; 1.2151x over previous
#include <cuda_runtime.h>
#include <cuda_bf16.h>
#include <math.h>
#include <stdint.h>

// ---------------- problem constants ----------------
#define NND 32768
#define NE  262144
#define NS  128
#define D_0 190
#define D_X 380
#define D_GIN 256
#define D_GH 512

// ---------------- device scratch (static, no allocation) ----------------
__device__ __align__(128) float g_x1[(size_t)NND * D_X];
__device__ __align__(128) float g_x2[(size_t)NND * D_GIN];
__device__ __align__(128) float g_xa[(size_t)NND * D_GH];
__device__ __align__(128) float g_xb[(size_t)NND * D_GH];
__device__ __align__(128) __nv_bfloat16 g_ahi[(size_t)NND * 1024];
__device__ __align__(128) __nv_bfloat16 g_alo[(size_t)NND * 1024];
__device__ __align__(128) __nv_bfloat16 g_whi[512 * 1024];
__device__ __align__(128) __nv_bfloat16 g_wlo[512 * 1024];
__device__ float g_invdeg[NND];
__device__ int   g_segid[NND];
__device__ int   g_deg[NND];
__device__ int   g_rowstart[NND + 1];
__device__ int   g_cursor[NND];
__device__ int   g_csrsrc[NE];
__device__ float g_glnstat[NS * 2];
__device__ float g_colsum[D_GH];
__device__ float g_pnmean[D_GH];
__device__ float g_scalar[2];
__device__ float g_segout[NS];

// ---------------- PTX helpers (compute_103-safe) ----------------
__device__ __forceinline__ uint32_t smem_u32(const void* p) {
    uint32_t a;
    asm("{ .reg .u64 t; cvta.to.shared.u64 t, %1; cvt.u32.u64 %0, t; }" : "=r"(a) : "l"(p));
    return a;
}
__device__ __forceinline__ void cpasync16(uint32_t dst, const void* src) {
    asm volatile("cp.async.cg.shared.global [%0], [%1], 16;" :: "r"(dst), "l"(src) : "memory");
}
__device__ __forceinline__ void ldm_x4(uint32_t* r, uint32_t addr) {
    asm volatile("ldmatrix.sync.aligned.m8n8.x4.shared.b16 {%0,%1,%2,%3},[%4];"
                 : "=r"(r[0]), "=r"(r[1]), "=r"(r[2]), "=r"(r[3]) : "r"(addr));
}
__device__ __forceinline__ void ldm_x2(uint32_t* r, uint32_t addr) {
    asm volatile("ldmatrix.sync.aligned.m8n8.x2.shared.b16 {%0,%1},[%2];"
                 : "=r"(r[0]), "=r"(r[1]) : "r"(addr));
}
__device__ __forceinline__ void mma_bf16(float* d, const uint32_t* a, const uint32_t* b) {
    asm volatile(
        "mma.sync.aligned.m16n8k16.row.col.f32.bf16.bf16.f32 "
        "{%0,%1,%2,%3}, {%4,%5,%6,%7}, {%8,%9}, {%0,%1,%2,%3};"
        : "+f"(d[0]), "+f"(d[1]), "+f"(d[2]), "+f"(d[3])
        : "r"(a[0]), "r"(a[1]), "r"(a[2]), "r"(a[3]), "r"(b[0]), "r"(b[1]));
}
__device__ __forceinline__ void split_bf16(float v, __nv_bfloat16& h, __nv_bfloat16& l) {
    h = __float2bfloat16(v);
    l = __float2bfloat16(v - __bfloat162float(h));
}

// ---------------- small utility kernels ----------------
__global__ void k_zero(float* p, size_t n) {
    size_t i = (size_t)blockIdx.x * blockDim.x + threadIdx.x;
    if (i < n) p[i] = 0.f;
}
__global__ void k_segid(const int* __restrict__ sep) {
    int i = blockIdx.x * blockDim.x + threadIdx.x;
    if (i >= NND) return;
    int lo = 0, hi = NS;
    while (lo < hi) { int mid = (lo + hi) >> 1; if (sep[mid] <= i) lo = mid + 1; else hi = mid; }
    g_segid[i] = lo;
    g_deg[i] = 0;
}
__global__ void k_hist(const int* __restrict__ dst) {
    int e = blockIdx.x * blockDim.x + threadIdx.x;
    if (e < NE) atomicAdd(&g_deg[dst[e]], 1);
}
// one-block scan over 32768 degrees -> rowstart/cursor/invdeg
__global__ void __launch_bounds__(1024) k_scan() {
    __shared__ int sh[1024];
    int t = threadIdx.x;
    int base = t * 32;
    int loc[32];
    int s = 0;
#pragma unroll
    for (int i = 0; i < 32; i++) { loc[i] = s; s += g_deg[base + i]; }
    sh[t] = s;
    __syncthreads();
    for (int o = 1; o < 1024; o <<= 1) {
        int v = (t >= o) ? sh[t - o] : 0;
        __syncthreads();
        sh[t] += v;
        __syncthreads();
    }
    int start = (t == 0) ? 0 : sh[t - 1];
#pragma unroll
    for (int i = 0; i < 32; i++) {
        int n = base + i;
        int st = start + loc[i];
        g_rowstart[n] = st;
        g_cursor[n] = st;
        int d = g_deg[n];
        g_invdeg[n] = 1.f / (float)((d > 1) ? d : 1);
    }
    if (t == 1023) g_rowstart[NND] = sh[1023];
}
__global__ void k_fillcsr(const int* __restrict__ src, const int* __restrict__ dst) {
    int e = blockIdx.x * blockDim.x + threadIdx.x;
    if (e >= NE) return;
    int d = dst[e];
    int pos = atomicAdd(&g_cursor[d], 1);
    g_csrsrc[pos] = src[e];
}
// concat -> bf16 hi/lo directly (stride 192, cols 190-191 zero)
__global__ void k_concat_cvt(const float* __restrict__ nf, const float* __restrict__ ncf,
                             const float* __restrict__ emb, const int* __restrict__ ops,
                             __nv_bfloat16* __restrict__ hi, __nv_bfloat16* __restrict__ lo) {
    size_t i = (size_t)blockIdx.x * blockDim.x + threadIdx.x;
    if (i >= (size_t)NND * 192) return;
    int r = (int)(i / 192);
    int c = (int)(i - (size_t)r * 192);
    float v = 0.f;
    if (c < 90)       v = nf[(size_t)r * 90 + c];
    else if (c < 126) v = ncf[(size_t)r * 36 + (c - 90)];
    else if (c < 190) v = emb[(size_t)ops[r] * 64 + (c - 126)];
    __nv_bfloat16 h, l;
    split_bf16(v, h, l);
    hi[i] = h; lo[i] = l;
}
__global__ void k_cvtW(const float* __restrict__ W, __nv_bfloat16* __restrict__ hi,
                       __nv_bfloat16* __restrict__ lo, int Nd, int K, int Ndp, int Kp) {
    int idx = blockIdx.x * blockDim.x + threadIdx.x;
    if (idx >= Ndp * Kp) return;
    int n = idx / Kp, k = idx - n * Kp;
    float v = (n < Nd && k < K) ? W[(size_t)n * K + k] : 0.f;
    __nv_bfloat16 h, l;
    split_bf16(v, h, l);
    hi[idx] = h; lo[idx] = l;
}
__global__ void k_cvtWpair(const float* __restrict__ wl, const float* __restrict__ wr,
                           __nv_bfloat16* __restrict__ hi, __nv_bfloat16* __restrict__ lo, int K1) {
    int Kt = 2 * K1;
    int idx = blockIdx.x * blockDim.x + threadIdx.x;
    if (idx >= 512 * Kt) return;
    int n = idx / Kt, k = idx - n * Kt;
    float v = (k < K1) ? wl[(size_t)n * K1 + k] : wr[(size_t)n * K1 + (k - K1)];
    __nv_bfloat16 h, l;
    split_bf16(v, h, l);
    hi[idx] = h; lo[idx] = l;
}

// ---------------- CSR gather aggregation (mean of neighbors) ----------------
// one warp per node; accumulate in registers; write bf16 hi/lo to A buffer col 0.
// D must be 256 or 512.
template <int D>
__global__ void __launch_bounds__(256)
k_gather_cvt(const float* __restrict__ x, int strideK,
             __nv_bfloat16* __restrict__ hi, __nv_bfloat16* __restrict__ lo) {
    const int warp = (blockIdx.x * blockDim.x + threadIdx.x) >> 5;
    if (warp >= NND) return;
    const int lane = threadIdx.x & 31;
    const int s0 = g_rowstart[warp];
    const int s1 = g_rowstart[warp + 1];
    constexpr int NSW = D / 128;             // float4 sweeps per lane
    float acc[NSW][4];
#pragma unroll
    for (int w = 0; w < NSW; w++) { acc[w][0] = acc[w][1] = acc[w][2] = acc[w][3] = 0.f; }
    for (int e = s0; e < s1; e++) {
        int s = g_csrsrc[e];
        const float4* row = (const float4*)&x[(size_t)s * D];
#pragma unroll
        for (int w = 0; w < NSW; w++) {
            float4 v = row[w * 32 + lane];
            acc[w][0] += v.x; acc[w][1] += v.y; acc[w][2] += v.z; acc[w][3] += v.w;
        }
    }
    const float inv = g_invdeg[warp];
    const size_t ob = (size_t)warp * strideK;
#pragma unroll
    for (int w = 0; w < NSW; w++) {
        size_t o = ob + w * 128 + lane * 4;
        __nv_bfloat16 h0, l0, h1, l1, h2, l2, h3, l3;
        split_bf16(acc[w][0] * inv, h0, l0);
        split_bf16(acc[w][1] * inv, h1, l1);
        split_bf16(acc[w][2] * inv, h2, l2);
        split_bf16(acc[w][3] * inv, h3, l3);
        __nv_bfloat162* dh = (__nv_bfloat162*)(hi + o);
        __nv_bfloat162* dl = (__nv_bfloat162*)(lo + o);
        dh[0] = __nv_bfloat162{h0, h1}; dh[1] = __nv_bfloat162{h2, h3};
        dl[0] = __nv_bfloat162{l0, l1}; dl[1] = __nv_bfloat162{l2, l3};
    }
}

// ---------------- mma.sync bf16x3 GEMM ----------------
#define MAT_BYTES 18432
#define STG_BYTES 73728
#define GSMEM (2 * STG_BYTES)

__global__ void __launch_bounds__(256, 1)
k_mmagemm(const __nv_bfloat16* __restrict__ Ahi, const __nv_bfloat16* __restrict__ Alo,
          const __nv_bfloat16* __restrict__ Whi, const __nv_bfloat16* __restrict__ Wlo,
          const float* __restrict__ bias, float* __restrict__ C,
          const float* __restrict__ wc, int Kp, int Nd, int flags)
{
    extern __shared__ char smc[];
    const uint32_t sbase = smem_u32(smc);
    const int tid = threadIdx.x;
    const int lane = tid & 31;
    const int wid = tid >> 5;
    const int wm = wid & 1;
    const int wn = wid >> 1;
    const int bm = blockIdx.y * 128;
    const int bn = blockIdx.x * 128;

    const __nv_bfloat16* gsrc[4] = {Ahi, Alo, Whi, Wlo};
    const int rbase[4] = {bm, bm, bn, bn};
    const int nc = Kp >> 6;

    const uint32_t abyte = (uint32_t)((wm * 64 + (lane & 15)) * 144 + ((lane >> 4) & 1) * 16);
    const uint32_t bbyte = (uint32_t)((wn * 32 + (lane & 7)) * 144 + ((lane >> 3) & 1) * 16);

    float acc[4][4][4];
#pragma unroll
    for (int i = 0; i < 4; i++)
#pragma unroll
        for (int j = 0; j < 4; j++)
#pragma unroll
            for (int q = 0; q < 4; q++) acc[i][j][q] = 0.f;

    auto load_chunk = [&](int c, int stage) {
        const int k0 = c * 64;
        const uint32_t sdst0 = sbase + (uint32_t)stage * STG_BYTES;
#pragma unroll
        for (int t = 0; t < 16; t++) {
            int idx = tid + t * 256;
            int mat = idx >> 10;
            int u = idx & 1023;
            int row = u >> 3, seg = u & 7;
            uint32_t dst = sdst0 + (uint32_t)mat * MAT_BYTES + (uint32_t)(row * 144 + seg * 16);
            const __nv_bfloat16* src = gsrc[mat] + (size_t)(rbase[mat] + row) * Kp + k0 + seg * 8;
            cpasync16(dst, src);
        }
        asm volatile("cp.async.commit_group;" ::: "memory");
    };

    load_chunk(0, 0);

    for (int c = 0; c < nc; c++) {
        if (c + 1 < nc) {
            load_chunk(c + 1, (c + 1) & 1);
            asm volatile("cp.async.wait_group 1;" ::: "memory");
        } else {
            asm volatile("cp.async.wait_group 0;" ::: "memory");
        }
        __syncthreads();

        const uint32_t st = sbase + (uint32_t)(c & 1) * STG_BYTES;
        const uint32_t aHI = st + abyte;
        const uint32_t aLO = st + MAT_BYTES + abyte;
        const uint32_t wHI = st + 2 * MAT_BYTES + bbyte;
        const uint32_t wLO = st + 3 * MAT_BYTES + bbyte;

#pragma unroll
        for (int ks = 0; ks < 4; ks++) {
            uint32_t ah[4][4], al[4][4], wh[4][2], wl[4][2];
#pragma unroll
            for (int i = 0; i < 4; i++) {
                ldm_x4(ah[i], aHI + (uint32_t)(i * 2304 + ks * 32));
                ldm_x4(al[i], aLO + (uint32_t)(i * 2304 + ks * 32));
            }
#pragma unroll
            for (int j = 0; j < 4; j++) {
                ldm_x2(wh[j], wHI + (uint32_t)(j * 1152 + ks * 32));
                ldm_x2(wl[j], wLO + (uint32_t)(j * 1152 + ks * 32));
            }
#pragma unroll
            for (int i = 0; i < 4; i++)
#pragma unroll
                for (int j = 0; j < 4; j++) {
                    mma_bf16(acc[i][j], ah[i], wh[j]);
                    mma_bf16(acc[i][j], ah[i], wl[j]);
                    mma_bf16(acc[i][j], al[i], wh[j]);
                }
        }
        __syncthreads();
    }

    if (!(flags & 4)) {
#pragma unroll
        for (int i = 0; i < 4; i++) {
            int row0 = bm + wm * 64 + i * 16 + (lane >> 2);
#pragma unroll
            for (int j = 0; j < 4; j++) {
                int col = bn + wn * 32 + j * 8 + ((lane & 3) << 1);
                if (col >= Nd) continue;
                float bx = 0.f, by = 0.f;
                if (bias) { float2 b = *(const float2*)(bias + col); bx = b.x; by = b.y; }
#pragma unroll
                for (int h = 0; h < 2; h++) {
                    int row = row0 + h * 8;
                    float v0 = acc[i][j][2 * h + 0] + bx;
                    float v1 = acc[i][j][2 * h + 1] + by;
                    if (flags & 2) {
                        v0 = (v0 >= 0.f) ? v0 : 0.01f * v0;
                        v1 = (v1 >= 0.f) ? v1 : 0.01f * v1;
                    }
                    *(float2*)(C + (size_t)row * Nd + col) = make_float2(v0, v1);
                }
            }
        }
    } else {
        float part[4][2];
#pragma unroll
        for (int i = 0; i < 4; i++) { part[i][0] = 0.f; part[i][1] = 0.f; }
#pragma unroll
        for (int i = 0; i < 4; i++) {
#pragma unroll
            for (int j = 0; j < 4; j++) {
                int col = bn + wn * 32 + j * 8 + ((lane & 3) << 1);
                if (col >= Nd) continue;
                float2 w = *(const float2*)(wc + col);
                float bx = 0.f, by = 0.f;
                if (bias) { float2 b = *(const float2*)(bias + col); bx = b.x; by = b.y; }
#pragma unroll
                for (int h = 0; h < 2; h++) {
                    float v0 = acc[i][j][2 * h + 0] + bx;
                    float v1 = acc[i][j][2 * h + 1] + by;
                    part[i][h] += v0 * w.x + v1 * w.y;
                }
            }
        }
#pragma unroll
        for (int i = 0; i < 4; i++)
#pragma unroll
            for (int h = 0; h < 2; h++) {
                float p = part[i][h];
                p += __shfl_xor_sync(0xFFFFFFFFu, p, 1);
                p += __shfl_xor_sync(0xFFFFFFFFu, p, 2);
                if ((lane & 3) == 0) {
                    int row = bm + wm * 64 + i * 16 + h * 8 + (lane >> 2);
                    atomicAdd(&g_segout[g_segid[row]], p);
                }
            }
    }
}

// ---------------- graph-wise layernorm ----------------
__global__ void k_glnstats(const float* __restrict__ x, const int* __restrict__ sep, int D) {
    int s = blockIdx.x;
    int start = (s == 0) ? 0 : sep[s - 1];
    int end = sep[s];
    size_t total = (size_t)(end - start) * D;
    const float* base = &x[(size_t)start * D];
    float sum = 0.f, ss = 0.f;
    for (size_t i = threadIdx.x; i < total; i += blockDim.x) {
        float v = base[i];
        sum += v; ss += v * v;
    }
    __shared__ float s1[256], s2[256];
    int t = threadIdx.x;
    s1[t] = sum; s2[t] = ss;
    __syncthreads();
    for (int o = 128; o > 0; o >>= 1) {
        if (t < o) { s1[t] += s1[t + o]; s2[t] += s2[t + o]; }
        __syncthreads();
    }
    if (t == 0) {
        float cnt = (float)total;
        float mean = s1[0] / cnt;
        float var = s2[0] / cnt - mean * mean;
        g_glnstat[2 * s] = mean;
        g_glnstat[2 * s + 1] = rsqrtf(var + 1e-5f);
    }
}
__global__ void k_glnapply_cvt(float* __restrict__ x, const float* __restrict__ gamma,
                               const float* __restrict__ beta, int D, int Kpad,
                               int colOff, int strideK,
                               __nv_bfloat16* __restrict__ hi, __nv_bfloat16* __restrict__ lo,
                               int writeF32) {
    int r = blockIdx.x;
    int f = blockIdx.y * blockDim.x + threadIdx.x;
    if (f >= Kpad) return;
    float v = 0.f;
    if (f < D) {
        int s = g_segid[r];
        size_t i = (size_t)r * D + f;
        v = (x[i] - g_glnstat[2 * s]) * g_glnstat[2 * s + 1] * gamma[f] + beta[f];
        if (writeF32) x[i] = v;
    }
    __nv_bfloat16 h, l;
    split_bf16(v, h, l);
    size_t o = (size_t)r * strideK + colOff + f;
    hi[o] = h; lo[o] = l;
}

// ---------------- PairNorm ----------------
__global__ void k_pnstats(const float* __restrict__ x) {
    int r0 = blockIdx.x * 128;
    int t = threadIdx.x;
    float c1 = 0.f, c2 = 0.f, sq = 0.f;
    for (int r = 0; r < 128; r++) {
        const float* row = &x[(size_t)(r0 + r) * D_GH];
        float v1 = row[t], v2 = row[t + 256];
        c1 += v1; c2 += v2;
        sq += v1 * v1 + v2 * v2;
    }
    atomicAdd(&g_colsum[t], c1);
    atomicAdd(&g_colsum[t + 256], c2);
    __shared__ float sh[256];
    sh[t] = sq;
    __syncthreads();
    for (int o = 128; o > 0; o >>= 1) {
        if (t < o) sh[t] += sh[t + o];
        __syncthreads();
    }
    if (t == 0) atomicAdd(&g_scalar[0], sh[0]);
}
__global__ void k_pnfin() {
    int t = threadIdx.x;
    float m = g_colsum[t] / (float)NND;
    g_pnmean[t] = m;
    __shared__ float sh[512];
    sh[t] = m * m;
    __syncthreads();
    for (int o = 256; o > 0; o >>= 1) {
        if (t < o) sh[t] += sh[t + o];
        __syncthreads();
    }
    if (t == 0) {
        float var = g_scalar[0] / (float)NND - sh[0];
        g_scalar[1] = 1.f / (1e-5f + sqrtf(fmaxf(var, 0.f)));
    }
}
__global__ void k_pnapply_cvt(const float* __restrict__ in, float* __restrict__ out,
                              __nv_bfloat16* __restrict__ hi, __nv_bfloat16* __restrict__ lo) {
    size_t i = (size_t)blockIdx.x * blockDim.x + threadIdx.x;
    if (i >= (size_t)NND * D_GH) return;
    int f = (int)(i & (D_GH - 1));
    int r = (int)(i >> 9);
    float v = (in[i] - g_pnmean[f]) * g_scalar[1];
    v = fmaxf(v, 0.f);
    out[i] = v;
    __nv_bfloat16 h, l;
    split_bf16(v, h, l);
    size_t o = (size_t)r * 1024 + 512 + f;
    hi[o] = h; lo[o] = l;
}

__global__ void k_out(float* __restrict__ out, const float* __restrict__ bc) {
    int t = threadIdx.x;
    if (t < NS) out[t] = g_segout[t] + bc[0];
}

// ---------------- host orchestration ----------------
static __nv_bfloat16 *h_ahi, *h_alo, *h_whi, *h_wlo;

static inline void run_gemm(const float* bias, float* C, const float* wc,
                            int Kp, int Nd, int Ndp, int flags) {
    dim3 grid(Ndp / 128, NND / 128);
    k_mmagemm<<<grid, 256, GSMEM>>>(h_ahi, h_alo, h_whi, h_wlo, bias, C, wc, Kp, Nd, flags);
}

extern "C" void kernel_launch(void* const* d_in, const int* in_sizes, int n_in,
                              void* d_out, int out_size) {
    const float* nf   = (const float*)d_in[0];
    const float* ncf  = (const float*)d_in[1];
    const float* emb  = (const float*)d_in[2];
    const float* w1   = (const float*)d_in[3];
    const float* b1   = (const float*)d_in[4];
    const float* g1   = (const float*)d_in[5];
    const float* be1  = (const float*)d_in[6];
    const float* w2   = (const float*)d_in[7];
    const float* b2   = (const float*)d_in[8];
    const float* g2   = (const float*)d_in[9];
    const float* be2  = (const float*)d_in[10];
    const float* wl1  = (const float*)d_in[11];
    const float* bl1  = (const float*)d_in[12];
    const float* wr1  = (const float*)d_in[13];
    const float* wl2  = (const float*)d_in[14];
    const float* bl2  = (const float*)d_in[15];
    const float* wr2  = (const float*)d_in[16];
    const float* wl3  = (const float*)d_in[17];
    const float* bl3  = (const float*)d_in[18];
    const float* wr3  = (const float*)d_in[19];
    const float* wc   = (const float*)d_in[20];
    const float* bc   = (const float*)d_in[21];
    const int* ops    = (const int*)d_in[22];
    const int* edges  = (const int*)d_in[23];
    const int* sep    = (const int*)d_in[24];
    float* out        = (float*)d_out;

    const int* src = edges;
    const int* dst = edges + NE;

    cudaFuncSetAttribute(k_mmagemm, cudaFuncAttributeMaxDynamicSharedMemorySize, GSMEM);

    void *p_colsum, *p_scalar, *p_segout, *p_x1, *p_x2, *p_xa, *p_xb;
    void *p_ahi, *p_alo, *p_whi, *p_wlo;
    cudaGetSymbolAddress(&p_colsum, g_colsum);
    cudaGetSymbolAddress(&p_scalar, g_scalar);
    cudaGetSymbolAddress(&p_segout, g_segout);
    cudaGetSymbolAddress(&p_x1, g_x1);
    cudaGetSymbolAddress(&p_x2, g_x2);
    cudaGetSymbolAddress(&p_xa, g_xa);
    cudaGetSymbolAddress(&p_xb, g_xb);
    cudaGetSymbolAddress(&p_ahi, g_ahi);
    cudaGetSymbolAddress(&p_alo, g_alo);
    cudaGetSymbolAddress(&p_whi, g_whi);
    cudaGetSymbolAddress(&p_wlo, g_wlo);
    float* d_x1 = (float*)p_x1;
    float* d_x2 = (float*)p_x2;
    float* d_xa = (float*)p_xa;
    float* d_xb = (float*)p_xb;
    h_ahi = (__nv_bfloat16*)p_ahi;
    h_alo = (__nv_bfloat16*)p_alo;
    h_whi = (__nv_bfloat16*)p_whi;
    h_wlo = (__nv_bfloat16*)p_wlo;

    // ---- prep: segids, CSR build, input concat ----
    k_segid<<<(NND + 255) / 256, 256>>>(sep);
    k_hist<<<(NE + 255) / 256, 256>>>(dst);
    k_scan<<<1, 1024>>>();
    k_fillcsr<<<(NE + 255) / 256, 256>>>(src, dst);
    k_concat_cvt<<<(NND * 192 + 255) / 256, 256>>>(nf, ncf, emb, ops, h_ahi, h_alo);

    // ---- MLP layer 1: K=192, Nd=380 (Ndp 384) ----
    k_cvtW<<<(384 * 192 + 255) / 256, 256>>>(w1, h_whi, h_wlo, D_X, D_0, 384, 192);
    run_gemm(b1, d_x1, nullptr, 192, D_X, 384, /*leaky*/2);
    k_glnstats<<<NS, 256>>>(d_x1, sep, D_X);
    k_glnapply_cvt<<<dim3(NND, 2), 256>>>(d_x1, g1, be1, D_X, 384, 0, 384, h_ahi, h_alo, 0);

    // ---- MLP layer 2: K=384, Nd=256 ----
    k_cvtW<<<(256 * 384 + 255) / 256, 256>>>(w2, h_whi, h_wlo, D_GIN, D_X, 256, 384);
    run_gemm(b2, d_x2, nullptr, 384, D_GIN, 256, 2);
    k_glnstats<<<NS, 256>>>(d_x2, sep, D_GIN);
    // normalized x2: fp32 in-place (for gather) + bf16 at cols [256,512) of K=512 buffer
    k_glnapply_cvt<<<dim3(NND, 1), 256>>>(d_x2, g2, be2, D_GIN, 256, 256, 512, h_ahi, h_alo, 1);

    // ---- SAGE layer 1: combined K=512 ([mean-agg | x] @ [wl1 | wr1]) ----
    {
        k_cvtWpair<<<(512 * 512 + 255) / 256, 256>>>(wl1, wr1, h_whi, h_wlo, D_GIN);
        k_gather_cvt<D_GIN><<<NND / 8, 256>>>(d_x2, 512, h_ahi, h_alo);
        run_gemm(bl1, d_xb, nullptr, 512, D_GH, 512, 0);
        k_zero<<<3, 256>>>((float*)p_colsum, D_GH);
        k_zero<<<1, 2>>>((float*)p_scalar, 2);
        k_pnstats<<<NND / 128, 256>>>(d_xb);
        k_pnfin<<<1, 512>>>();
        size_t m = (size_t)NND * D_GH;
        k_pnapply_cvt<<<(unsigned)((m + 255) / 256), 256>>>(d_xb, d_xa, h_ahi, h_alo);
    }

    // ---- SAGE layer 2: combined K=1024 ----
    {
        size_t n = (size_t)NND * D_GH;
        k_cvtWpair<<<(512 * 1024 + 255) / 256, 256>>>(wl2, wr2, h_whi, h_wlo, D_GH);
        k_gather_cvt<D_GH><<<NND / 8, 256>>>(d_xa, 1024, h_ahi, h_alo);
        run_gemm(bl2, d_xb, nullptr, 1024, D_GH, 512, 0);
        k_zero<<<3, 256>>>((float*)p_colsum, D_GH);
        k_zero<<<1, 2>>>((float*)p_scalar, 2);
        k_pnstats<<<NND / 128, 256>>>(d_xb);
        k_pnfin<<<1, 512>>>();
        k_pnapply_cvt<<<(unsigned)((n + 255) / 256), 256>>>(d_xb, d_xa, h_ahi, h_alo);
    }

    // ---- SAGE layer 3: combined K=1024, fused final dot ----
    {
        k_cvtWpair<<<(512 * 1024 + 255) / 256, 256>>>(wl3, wr3, h_whi, h_wlo, D_GH);
        k_gather_cvt<D_GH><<<NND / 8, 256>>>(d_xa, 1024, h_ahi, h_alo);
        k_zero<<<1, NS>>>((float*)p_segout, NS);
        run_gemm(bl3, d_xb, wc, 1024, D_GH, 512, /*fused dot*/4);
    }

    k_out<<<1, NS>>>(out, bc);
}